// round 8
// baseline (speedup 1.0000x reference)
#include <cuda_runtime.h>
#include <math.h>

// DGPLoss fused single-kernel, row blocks + barrier-free depth-2 pipeline:
//   seg_feat: [4, 64, 512, 512] fp32   (d_in[0])
//   dep_true: [4, 1, 512, 512]  fp32   (d_in[1])
//   out[0]  : scalar fp32
//
// Block = one image row x batch (2040 blocks, 128 thr, 12 blocks/SM -> 48
// warps/SM, 42-reg cap). Thread = 4 adjacent px (LDG.128) + 2 scalar patch-
// center loads per channel. No smem / barriers in the main loop: channel
// g+1's three loads are issued (clamped index, no conditional copies) before
// channel g's FMAs, so each warp keeps ~2 full load groups in flight.
// Ticket-elected last block does the deterministic reduction over 2040
// partials.

#define EPSF 1e-8f
#define EPS2 1e-16f
#define CS   262144           // 512*512
#define CS4  (CS / 4)
#define NH   510
#define NBAT 4
#define NPART (NH * NBAT)     // 2040

__device__ float2       g_part[NPART];
__device__ unsigned int g_ticket;    // zero-init; reset by last block each run

__global__ __launch_bounds__(128, 12)
void dgp_fused(const float* __restrict__ seg, const float* __restrict__ dep,
               float* __restrict__ out)
{
    __shared__ float2 sw[4];
    __shared__ bool   isLast;

    const int tid = threadIdx.x;
    const int h   = blockIdx.x;          // 0..509
    const int b   = blockIdx.y;          // 0..3
    const int w0  = tid << 2;            // 0..508

    const int hc  = (h / 5) * 5 + 2;
    const int pA  = w0 / 5;
    const int pB  = (w0 + 3) / 5;
    const int wcA = pA * 5 + 2;
    const int wcB = pB * 5 + 2;
    const bool sB1 = ((w0 + 1) / 5) != pA;
    const bool sB2 = ((w0 + 2) / 5) != pA;
    const bool sB3 = (pB != pA);

    const int segBase = b * (64 * CS);   // fits int32 (max ~66.8M incl. 63*CS)
    const float4* __restrict__ pix = (const float4*)(seg + segBase + h * 512 + w0);
    const float*  __restrict__ ctA = seg + segBase + hc * 512 + wcA;
    const float*  __restrict__ ctB = seg + segBase + hc * 512 + wcB;

    float a0 = 0.f, a1 = 0.f, a2 = 0.f, a3 = 0.f;

    // prologue: channel 0 in flight
    float4 pc = pix[0];
    float  qa = ctA[0];
    float  qb = ctB[0];

    #pragma unroll 4
    for (int g = 0; g < 64; ++g) {
        // issue channel g+1's loads first (clamped: dup ch63 loads hit L1)
        const int gn = (g + 1 < 64) ? g + 1 : 63;
        const float4 pn  = pix[gn * CS4];
        const float  qan = ctA[gn * CS];
        const float  qbn = ctB[gn * CS];

        // compute channel g
        const float q1 = sB1 ? qb : qa;
        const float q2 = sB2 ? qb : qa;
        const float q3 = sB3 ? qb : qa;
        float d;
        d = qa - pc.x; a0 = fmaf(d, d, a0);
        d = q1 - pc.y; a1 = fmaf(d, d, a1);
        d = q2 - pc.z; a2 = fmaf(d, d, a2);
        d = q3 - pc.w; a3 = fmaf(d, d, a3);

        pc = pn; qa = qan; qb = qbn;
    }

    // ---- depth branch + mask ----
    const int depBase = b * CS;
    const float4 dq  = *(const float4*)(dep + depBase + h * 512 + w0);
    const float  dcA = dep[depBase + hc * 512 + wcA];
    const float  dcB = dep[depBase + hc * 512 + wcB];

    const float dcv[4] = { dcA, sB1 ? dcB : dcA, sB2 ? dcB : dcA, sB3 ? dcB : dcA };
    const int   wcv[4] = { wcA, sB1 ? wcB : wcA, sB2 ? wcB : wcA, sB3 ? wcB : wcA };
    const float av [4] = { a0, a1, a2, a3 };
    const float dpv[4] = { dq.x, dq.y, dq.z, dq.w };

    float sum = 0.f, cnt = 0.f;
    #pragma unroll
    for (int k = 0; k < 4; ++k) {
        const float dd = fabsf(dcv[k] - dpv[k]);
        const bool ic  = (h == hc) && (w0 + k == wcv[k]);
        const bool m   = (dd > EPSF) && (av[k] > EPS2) && (dpv[k] > EPSF) &&
                         !ic && (w0 + k < 510);
        if (m) {
            sum += __expf(-fmaf(dd, 0.1f, av[k]));
            cnt += 1.f;
        }
    }

    // ---- intra-block reduce (4 warps) ----
    #pragma unroll
    for (int o = 16; o > 0; o >>= 1) {
        sum += __shfl_down_sync(0xFFFFFFFFu, sum, o);
        cnt += __shfl_down_sync(0xFFFFFFFFu, cnt, o);
    }
    const int lane = tid & 31;
    const int wid  = tid >> 5;
    if (lane == 0) sw[wid] = make_float2(sum, cnt);
    __syncthreads();

    if (tid == 0) {
        const float2 t0 = sw[0], t1 = sw[1], t2 = sw[2], t3 = sw[3];
        g_part[blockIdx.x + NH * blockIdx.y] =
            make_float2(t0.x + t1.x + t2.x + t3.x, t0.y + t1.y + t2.y + t3.y);
        __threadfence();
        const unsigned t = atomicAdd(&g_ticket, 1u);
        isLast = (t == NPART - 1);
    }
    __syncthreads();

    // ---- final deterministic reduction by the last block ----
    if (isLast) {
        __threadfence();
        float s = 0.f, c = 0.f;
        #pragma unroll 4
        for (int i = tid; i < NPART; i += 128) {
            const float2 v = g_part[i];
            s += v.x; c += v.y;
        }
        #pragma unroll
        for (int o = 16; o > 0; o >>= 1) {
            s += __shfl_down_sync(0xFFFFFFFFu, s, o);
            c += __shfl_down_sync(0xFFFFFFFFu, c, o);
        }
        if (lane == 0) sw[wid] = make_float2(s, c);
        __syncthreads();
        if (tid == 0) {
            const float2 t0 = sw[0], t1 = sw[1], t2 = sw[2], t3 = sw[3];
            out[0] = (t0.x + t1.x + t2.x + t3.x) /
                     fmaxf(t0.y + t1.y + t2.y + t3.y, 1.0f);
            g_ticket = 0u;   // reset for next graph replay
        }
    }
}

extern "C" void kernel_launch(void* const* d_in, const int* in_sizes, int n_in,
                              void* d_out, int out_size) {
    const float* seg = (const float*)d_in[0];   // [4,64,512,512]
    const float* dep = (const float*)d_in[1];   // [4,1,512,512]
    float* out = (float*)d_out;

    dim3 grid(NH, NBAT);
    dgp_fused<<<grid, 128>>>(seg, dep, out);
}

// round 9
// speedup vs baseline: 1.2062x; 1.2062x over previous
#include <cuda_runtime.h>
#include <math.h>

// DGPLoss fused single-kernel: band blocks, barrier-free, L1-deduped centers.
//   seg_feat: [4, 64, 512, 512] fp32   (d_in[0])
//   dep_true: [4, 1, 512, 512]  fp32   (d_in[1])
//   out[0]  : scalar fp32
//
// Block = one 5-row patch band x batch (408 blocks, 640 thr, 3 blocks/SM ->
// 60 warps/SM). Thread = 4 adjacent px (LDG.128) + 2 scalar center loads per
// channel. No smem / barriers in the channel loop: the row-2 warps of the
// SAME block stream the center row as their own pixel data, so the scalar
// center loads of the other 16 warps are L1 hits (per-SM L1 dedups sectors;
// misses to the same sector merge). Row-2 warps' centers are duplicates of
// their own just-loaded quads -> trivially fast -> they run ahead and
// prefetch center lines for the rest. Ticket-elected last block reduces 408
// partials deterministically.

#define EPSF 1e-8f
#define EPS2 1e-16f
#define CS   262144              // 512*512
#define CS4  (CS / 4)
#define NBANDS 102
#define NBAT 4
#define NPART (NBANDS * NBAT)    // 408

__device__ float2       g_part[NPART];
__device__ unsigned int g_ticket;   // zero-init; reset by last block each run

__global__ __launch_bounds__(640, 3)
void dgp_fused(const float* __restrict__ seg, const float* __restrict__ dep,
               float* __restrict__ out)
{
    __shared__ float2 s_red[20];
    __shared__ bool   isLast;

    const int tid = threadIdx.x;
    const int r   = tid >> 7;        // row within band: 0..4
    const int wl  = tid & 127;
    const int w0  = wl << 2;         // 0..508
    const int j   = blockIdx.x;      // band 0..101
    const int b   = blockIdx.y;      // batch 0..3
    const int h   = j * 5 + r;
    const int hc  = j * 5 + 2;

    const int pA  = w0 / 5;
    const int pB  = (w0 + 3) / 5;
    const int wcA = pA * 5 + 2;
    const int wcB = pB * 5 + 2;
    const bool sB1 = ((w0 + 1) / 5) != pA;
    const bool sB2 = ((w0 + 2) / 5) != pA;
    const bool sB3 = (pB != pA);

    const int segBase = b * (64 * CS);   // fits int32
    const float4* __restrict__ pix = (const float4*)(seg + segBase + h * 512 + w0);
    const float*  __restrict__ ctA = seg + segBase + hc * 512 + wcA;
    const float*  __restrict__ ctB = seg + segBase + hc * 512 + wcB;

    float a0 = 0.f, a1 = 0.f, a2 = 0.f, a3 = 0.f;

    #pragma unroll 8
    for (int c = 0; c < 64; ++c) {
        const float4 p  = pix[c * CS4];
        const float  qA = ctA[c * CS];
        const float  qB = ctB[c * CS];
        const float  q1 = sB1 ? qB : qA;
        const float  q2 = sB2 ? qB : qA;
        const float  q3 = sB3 ? qB : qA;
        float d;
        d = qA - p.x; a0 = fmaf(d, d, a0);
        d = q1 - p.y; a1 = fmaf(d, d, a1);
        d = q2 - p.z; a2 = fmaf(d, d, a2);
        d = q3 - p.w; a3 = fmaf(d, d, a3);
    }

    // ---- depth branch + mask ----
    const int depBase = b * CS;
    const float4 dq  = *(const float4*)(dep + depBase + h * 512 + w0);
    const float  dcA = dep[depBase + hc * 512 + wcA];
    const float  dcB = dep[depBase + hc * 512 + wcB];

    const float dcv[4] = { dcA, sB1 ? dcB : dcA, sB2 ? dcB : dcA, sB3 ? dcB : dcA };
    const int   wcv[4] = { wcA, sB1 ? wcB : wcA, sB2 ? wcB : wcA, sB3 ? wcB : wcA };
    const float av [4] = { a0, a1, a2, a3 };
    const float dpv[4] = { dq.x, dq.y, dq.z, dq.w };

    float sum = 0.f, cnt = 0.f;
    #pragma unroll
    for (int k = 0; k < 4; ++k) {
        const float dd = fabsf(dcv[k] - dpv[k]);
        const bool ic  = (r == 2) && (w0 + k == wcv[k]);
        const bool m   = (dd > EPSF) && (av[k] > EPS2) && (dpv[k] > EPSF) &&
                         !ic && (w0 + k < 510);
        if (m) {
            sum += __expf(-fmaf(dd, 0.1f, av[k]));
            cnt += 1.f;
        }
    }

    // ---- block reduce (20 warps) ----
    #pragma unroll
    for (int o = 16; o > 0; o >>= 1) {
        sum += __shfl_down_sync(0xFFFFFFFFu, sum, o);
        cnt += __shfl_down_sync(0xFFFFFFFFu, cnt, o);
    }
    const int lane = tid & 31;
    const int wid  = tid >> 5;
    if (lane == 0) s_red[wid] = make_float2(sum, cnt);
    __syncthreads();

    if (wid == 0) {
        float s = (lane < 20) ? s_red[lane].x : 0.f;
        float c = (lane < 20) ? s_red[lane].y : 0.f;
        #pragma unroll
        for (int o = 16; o > 0; o >>= 1) {
            s += __shfl_down_sync(0xFFFFFFFFu, s, o);
            c += __shfl_down_sync(0xFFFFFFFFu, c, o);
        }
        if (lane == 0) {
            g_part[j + NBANDS * b] = make_float2(s, c);
            __threadfence();
            const unsigned t = atomicAdd(&g_ticket, 1u);
            isLast = (t == NPART - 1);
        }
    }
    __syncthreads();

    // ---- final deterministic reduction by the last block ----
    if (isLast) {
        __threadfence();
        float s = 0.f, c = 0.f;
        if (tid < NPART) {               // 408 < 640: one partial per thread
            const float2 v = g_part[tid];
            s = v.x; c = v.y;
        }
        #pragma unroll
        for (int o = 16; o > 0; o >>= 1) {
            s += __shfl_down_sync(0xFFFFFFFFu, s, o);
            c += __shfl_down_sync(0xFFFFFFFFu, c, o);
        }
        __syncthreads();                 // s_red reuse
        if (lane == 0) s_red[wid] = make_float2(s, c);
        __syncthreads();
        if (wid == 0) {
            float ts = (lane < 20) ? s_red[lane].x : 0.f;
            float tc = (lane < 20) ? s_red[lane].y : 0.f;
            #pragma unroll
            for (int o = 16; o > 0; o >>= 1) {
                ts += __shfl_down_sync(0xFFFFFFFFu, ts, o);
                tc += __shfl_down_sync(0xFFFFFFFFu, tc, o);
            }
            if (lane == 0) {
                out[0] = ts / fmaxf(tc, 1.0f);
                g_ticket = 0u;           // reset for next graph replay
            }
        }
    }
}

extern "C" void kernel_launch(void* const* d_in, const int* in_sizes, int n_in,
                              void* d_out, int out_size) {
    const float* seg = (const float*)d_in[0];   // [4,64,512,512]
    const float* dep = (const float*)d_in[1];   // [4,1,512,512]
    float* out = (float*)d_out;

    dim3 grid(NBANDS, NBAT);
    dgp_fused<<<grid, 640>>>(seg, dep, out);
}

// round 11
// speedup vs baseline: 1.3137x; 1.0891x over previous
#include <cuda_runtime.h>
#include <math.h>

// DGPLoss fused single-kernel: band blocks + 4-stage cp.async smem pipeline.
//   seg_feat: [4, 64, 512, 512] fp32   (d_in[0])
//   dep_true: [4, 1, 512, 512]  fp32   (d_in[1])
//   out[0]  : scalar fp32
//
// Block = one 5-row patch band x batch (408 blocks, 640 thr, 3 blocks/SM).
// Per channel: each thread cp.async's its 16B quad into a 10KB stage buffer
// (4 stages, 40KB). Channel g's data is requested 3 iterations before use,
// so DRAM latency is fully decoupled from the compute chain at ZERO register
// cost. Quads AND patch centers are read from the same smem tile (center row
// = band row 2). One wait_group + one __syncthreads per channel. Ticket-
// elected last block reduces 408 partials deterministically.

#define EPSF 1e-8f
#define EPS2 1e-16f
#define CS   262144              // 512*512
#define NBANDS 102
#define NBAT 4
#define NPART (NBANDS * NBAT)    // 408
#define STAGES 4
#define STAGE_BYTES (5 * 512 * 4)   // 10240

typedef unsigned int u32;

__device__ float2 g_part[NPART];
__device__ u32    g_ticket;   // zero-init; reset by last block each run

__device__ __forceinline__ u32 smem_u32(const void* p) {
    return (u32)__cvta_generic_to_shared(p);
}
__device__ __forceinline__ void cp_async16(u32 dst, const float* src) {
    asm volatile("cp.async.cg.shared.global [%0], [%1], 16;\n"
                 :: "r"(dst), "l"(src) : "memory");
}
__device__ __forceinline__ void cp_commit() {
    asm volatile("cp.async.commit_group;\n" ::: "memory");
}
__device__ __forceinline__ void cp_wait2() {
    asm volatile("cp.async.wait_group 2;\n" ::: "memory");
}

__global__ __launch_bounds__(640, 3)
void dgp_fused(const float* __restrict__ seg, const float* __restrict__ dep,
               float* __restrict__ out)
{
    __shared__ float  sbuf[STAGES][5][512];   // 40 KB
    __shared__ float2 s_red[20];
    __shared__ bool   isLast;

    const int tid = threadIdx.x;
    const int r   = tid >> 7;        // row within band: 0..4
    const int wl  = tid & 127;
    const int w0  = wl << 2;         // 0..508
    const int j   = blockIdx.x;      // band 0..101
    const int b   = blockIdx.y;      // batch 0..3
    const int h   = j * 5 + r;
    const int hc  = j * 5 + 2;

    const int pA  = w0 / 5;
    const int pB  = (w0 + 3) / 5;    // may be 102 -> wcB=512 reads row3 col0 (finite, masked)
    const int wcA = pA * 5 + 2;
    const int wcB = pB * 5 + 2;
    const bool sB1 = ((w0 + 1) / 5) != pA;
    const bool sB2 = ((w0 + 2) / 5) != pA;
    const bool sB3 = (pB != pA);

    const int segBase = b * (64 * CS);   // fits int32
    const float* __restrict__ src0 = seg + segBase + h * 512 + w0;

    const u32 sb     = smem_u32(sbuf);
    const u32 dstoff = (u32)((r * 512 + w0) * 4);

    // prologue: stages 0..2 in flight
    #pragma unroll
    for (int s = 0; s < 3; ++s) {
        cp_async16(sb + s * STAGE_BYTES + dstoff, src0 + s * CS);
        cp_commit();
    }

    float a0 = 0.f, a1 = 0.f, a2 = 0.f, a3 = 0.f;

    #pragma unroll 4
    for (int g = 0; g < 64; ++g) {
        cp_wait2();          // stage g arrived (this thread's copies)
        __syncthreads();     // stage g visible from ALL threads

        // issue stage g+3 into buf (g+3)&3 == (g-1)&3 (fully consumed pre-BAR)
        if (g + 3 < 64)
            cp_async16(sb + ((g + 3) & 3) * STAGE_BYTES + dstoff,
                       src0 + (g + 3) * CS);
        cp_commit();         // commit every iter (empty groups keep counts exact)

        const int st = g & 3;
        const float4 p  = *(const float4*)&sbuf[st][r][w0];
        const float  qA = sbuf[st][2][wcA];
        const float  qB = sbuf[st][2][wcB];
        const float  q1 = sB1 ? qB : qA;
        const float  q2 = sB2 ? qB : qA;
        const float  q3 = sB3 ? qB : qA;
        float d;
        d = qA - p.x; a0 = fmaf(d, d, a0);
        d = q1 - p.y; a1 = fmaf(d, d, a1);
        d = q2 - p.z; a2 = fmaf(d, d, a2);
        d = q3 - p.w; a3 = fmaf(d, d, a3);
    }

    // ---- depth branch + mask (direct global; tiny) ----
    const int depBase = b * CS;
    const float4 dq  = *(const float4*)(dep + depBase + h * 512 + w0);
    const float  dcA = dep[depBase + hc * 512 + wcA];
    const float  dcB = dep[depBase + hc * 512 + wcB];

    const float dcv[4] = { dcA, sB1 ? dcB : dcA, sB2 ? dcB : dcA, sB3 ? dcB : dcA };
    const int   wcv[4] = { wcA, sB1 ? wcB : wcA, sB2 ? wcB : wcA, sB3 ? wcB : wcA };
    const float av [4] = { a0, a1, a2, a3 };
    const float dpv[4] = { dq.x, dq.y, dq.z, dq.w };

    float sum = 0.f, cnt = 0.f;
    #pragma unroll
    for (int k = 0; k < 4; ++k) {
        const float dd = fabsf(dcv[k] - dpv[k]);
        const bool ic  = (r == 2) && (w0 + k == wcv[k]);
        const bool m   = (dd > EPSF) && (av[k] > EPS2) && (dpv[k] > EPSF) &&
                         !ic && (w0 + k < 510);
        if (m) {
            sum += __expf(-fmaf(dd, 0.1f, av[k]));
            cnt += 1.f;
        }
    }

    // ---- block reduce (20 warps) ----
    #pragma unroll
    for (int o = 16; o > 0; o >>= 1) {
        sum += __shfl_down_sync(0xFFFFFFFFu, sum, o);
        cnt += __shfl_down_sync(0xFFFFFFFFu, cnt, o);
    }
    const int lane = tid & 31;
    const int wid  = tid >> 5;
    if (lane == 0) s_red[wid] = make_float2(sum, cnt);
    __syncthreads();

    if (wid == 0) {
        float s = (lane < 20) ? s_red[lane].x : 0.f;
        float c = (lane < 20) ? s_red[lane].y : 0.f;
        #pragma unroll
        for (int o = 16; o > 0; o >>= 1) {
            s += __shfl_down_sync(0xFFFFFFFFu, s, o);
            c += __shfl_down_sync(0xFFFFFFFFu, c, o);
        }
        if (lane == 0) {
            g_part[j + NBANDS * b] = make_float2(s, c);
            __threadfence();
            const u32 t = atomicAdd(&g_ticket, 1u);
            isLast = (t == NPART - 1);
        }
    }
    __syncthreads();

    // ---- final deterministic reduction by the last block ----
    if (isLast) {
        __threadfence();
        float s = 0.f, c = 0.f;
        if (tid < NPART) {               // 408 < 640: one partial per thread
            const float2 v = g_part[tid];
            s = v.x; c = v.y;
        }
        #pragma unroll
        for (int o = 16; o > 0; o >>= 1) {
            s += __shfl_down_sync(0xFFFFFFFFu, s, o);
            c += __shfl_down_sync(0xFFFFFFFFu, c, o);
        }
        __syncthreads();                 // s_red reuse
        if (lane == 0) s_red[wid] = make_float2(s, c);
        __syncthreads();
        if (wid == 0) {
            float ts = (lane < 20) ? s_red[lane].x : 0.f;
            float tc = (lane < 20) ? s_red[lane].y : 0.f;
            #pragma unroll
            for (int o = 16; o > 0; o >>= 1) {
                ts += __shfl_down_sync(0xFFFFFFFFu, ts, o);
                tc += __shfl_down_sync(0xFFFFFFFFu, tc, o);
            }
            if (lane == 0) {
                out[0] = ts / fmaxf(tc, 1.0f);
                g_ticket = 0u;           // reset for next graph replay
            }
        }
    }
}

extern "C" void kernel_launch(void* const* d_in, const int* in_sizes, int n_in,
                              void* d_out, int out_size) {
    const float* seg = (const float*)d_in[0];   // [4,64,512,512]
    const float* dep = (const float*)d_in[1];   // [4,1,512,512]
    float* out = (float*)d_out;

    dim3 grid(NBANDS, NBAT);
    dgp_fused<<<grid, 640>>>(seg, dep, out);
}